// round 5
// baseline (speedup 1.0000x reference)
#include <cuda_runtime.h>

#define D 128
#define D4 (D / 4)              // 32 float4 per row
#define THREADS 128
#define GROUPS (THREADS / 32)   // 4 row-groups
#define CHUNKS 8                // chunks per segment

#define MAX_B 8192
__device__ int g_off[MAX_B + 1];   // segment start offsets (exclusive scan)

// ---- prep: zero output + exclusive-scan batch_lengths into g_off ----
__global__ __launch_bounds__(1024)
void prep_kernel(const int* __restrict__ lens, int B,
                 float* __restrict__ out, int out_n)
{
    const int t = threadIdx.x;

    // zero the output (float4 stores); out_n divisible by 4 (B*D)
    int idx = blockIdx.x * blockDim.x + t;
    float4 z = make_float4(0.f, 0.f, 0.f, 0.f);
    for (int i = idx; i * 4 < out_n; i += gridDim.x * blockDim.x)
        reinterpret_cast<float4*>(out)[i] = z;

    // block 0 scans lens -> g_off
    if (blockIdx.x == 0) {
        __shared__ int s[1024];
        int carry = 0;
        for (int base = 0; base < B; base += 1024) {
            int v = (base + t < B) ? lens[base + t] : 0;
            s[t] = v;
            for (int off = 1; off < 1024; off <<= 1) {
                __syncthreads();
                int u = (t >= off) ? s[t - off] : 0;
                __syncthreads();
                s[t] += u;
            }
            __syncthreads();
            if (base + t < B) g_off[base + t + 1] = carry + s[t];
            __syncthreads();
            carry += s[1023];
        }
        if (t == 0) g_off[0] = 0;
    }
}

// ---- main: one CTA per (segment, chunk), atomic accumulate mean ----
__global__ __launch_bounds__(THREADS, 8)
void seg_mean_kernel(const float* __restrict__ x,
                     float* __restrict__ out)
{
    const int b   = blockIdx.x >> 3;          // segment (CHUNKS = 8)
    const int c   = blockIdx.x & (CHUNKS - 1);
    const int tid = threadIdx.x;

    const int start = g_off[b];
    const int len   = g_off[b + 1] - start;
    const int r0    = (int)(((long long)c * len) / CHUNKS);
    const int r1    = (int)(((long long)(c + 1) * len) / CHUNKS);

    const float4* __restrict__ xv =
        reinterpret_cast<const float4*>(x) + (size_t)start * D4;
    const int cg = tid & 31;   // float4 column 0..31
    const int rg = tid >> 5;   // row group 0..3

    float4 a0 = make_float4(0.f, 0.f, 0.f, 0.f);
    float4 a1 = a0, a2 = a0, a3 = a0;

    int r = r0 + rg;
    // 8 independent in-flight LDG.128 per thread, 32 rows/iter
    for (; r + 7 * GROUPS < r1; r += 8 * GROUPS) {
        float4 v0 = xv[(size_t)(r + 0 * GROUPS) * D4 + cg];
        float4 v1 = xv[(size_t)(r + 1 * GROUPS) * D4 + cg];
        float4 v2 = xv[(size_t)(r + 2 * GROUPS) * D4 + cg];
        float4 v3 = xv[(size_t)(r + 3 * GROUPS) * D4 + cg];
        float4 v4 = xv[(size_t)(r + 4 * GROUPS) * D4 + cg];
        float4 v5 = xv[(size_t)(r + 5 * GROUPS) * D4 + cg];
        float4 v6 = xv[(size_t)(r + 6 * GROUPS) * D4 + cg];
        float4 v7 = xv[(size_t)(r + 7 * GROUPS) * D4 + cg];
        a0.x += v0.x; a0.y += v0.y; a0.z += v0.z; a0.w += v0.w;
        a1.x += v1.x; a1.y += v1.y; a1.z += v1.z; a1.w += v1.w;
        a2.x += v2.x; a2.y += v2.y; a2.z += v2.z; a2.w += v2.w;
        a3.x += v3.x; a3.y += v3.y; a3.z += v3.z; a3.w += v3.w;
        a0.x += v4.x; a0.y += v4.y; a0.z += v4.z; a0.w += v4.w;
        a1.x += v5.x; a1.y += v5.y; a1.z += v5.z; a1.w += v5.w;
        a2.x += v6.x; a2.y += v6.y; a2.z += v6.z; a2.w += v6.w;
        a3.x += v7.x; a3.y += v7.y; a3.z += v7.z; a3.w += v7.w;
    }
    for (; r < r1; r += GROUPS) {
        float4 v = xv[(size_t)r * D4 + cg];
        a0.x += v.x; a0.y += v.y; a0.z += v.z; a0.w += v.w;
    }
    a0.x += a1.x + a2.x + a3.x;
    a0.y += a1.y + a2.y + a3.y;
    a0.z += a1.z + a2.z + a3.z;
    a0.w += a1.w + a2.w + a3.w;

    // ---- cross-row-group reduction in smem ----
    __shared__ float4 sred[GROUPS][32];
    sred[rg][cg] = a0;
    __syncthreads();

    if (tid < 32) {
        float4 s = sred[0][tid];
        #pragma unroll
        for (int g = 1; g < GROUPS; g++) {
            float4 v = sred[g][tid];
            s.x += v.x; s.y += v.y; s.z += v.z; s.w += v.w;
        }
        const float inv = 1.0f / (float)len;
        float* o = out + (size_t)b * D + tid * 4;
        atomicAdd(o + 0, s.x * inv);
        atomicAdd(o + 1, s.y * inv);
        atomicAdd(o + 2, s.z * inv);
        atomicAdd(o + 3, s.w * inv);
    }
}

extern "C" void kernel_launch(void* const* d_in, const int* in_sizes, int n_in,
                              void* d_out, int out_size)
{
    const float* x    = (const float*)d_in[0];
    const int*   lens = (const int*)d_in[1];
    float*       out  = (float*)d_out;
    const int B = in_sizes[1];

    prep_kernel<<<32, 1024>>>(lens, B, out, out_size);
    seg_mean_kernel<<<B * CHUNKS, THREADS>>>(x, out);
}

// round 6
// speedup vs baseline: 1.0040x; 1.0040x over previous
#include <cuda_runtime.h>

#define D 128
#define D4 (D / 4)              // 32 float4 per row
#define THREADS 128
#define GROUPS (THREADS / 32)   // 4 row-groups
#define CHUNKS 8                // chunks per segment

#define MAX_B 8192
__device__ int g_off[MAX_B + 1];   // segment start offsets (exclusive scan)

// ---- prep: zero output (all blocks) + warp-shuffle scan of lens (block 0) ----
__global__ __launch_bounds__(1024)
void prep_kernel(const int* __restrict__ lens, int B,
                 float* __restrict__ out, int out_n)
{
    const int t = threadIdx.x;

    // zero output (float4 stores); out_n divisible by 4
    int idx = blockIdx.x * blockDim.x + t;
    float4 z = make_float4(0.f, 0.f, 0.f, 0.f);
    for (int i = idx; i * 4 < out_n; i += gridDim.x * blockDim.x)
        reinterpret_cast<float4*>(out)[i] = z;

    // block 0: exclusive scan lens -> g_off, warp-shuffle based
    if (blockIdx.x == 0) {
        __shared__ int warp_sums[32];
        const int lane = t & 31;
        const int wid  = t >> 5;
        int carry = 0;
        for (int base = 0; base < B; base += 1024) {
            int i = base + t;
            int v = (i < B) ? lens[i] : 0;
            // inclusive warp scan
            #pragma unroll
            for (int off = 1; off < 32; off <<= 1) {
                int u = __shfl_up_sync(0xFFFFFFFFu, v, off);
                if (lane >= off) v += u;
            }
            if (lane == 31) warp_sums[wid] = v;
            __syncthreads();
            if (wid == 0) {
                int w = warp_sums[lane];
                #pragma unroll
                for (int off = 1; off < 32; off <<= 1) {
                    int u = __shfl_up_sync(0xFFFFFFFFu, w, off);
                    if (lane >= off) w += u;
                }
                warp_sums[lane] = w;   // inclusive scan of warp sums
            }
            __syncthreads();
            int addw = (wid > 0) ? warp_sums[wid - 1] : 0;
            if (i < B) g_off[i + 1] = carry + addw + v;
            carry += warp_sums[31];
            __syncthreads();
        }
        if (t == 0) g_off[0] = 0;
    }
}

// ---- main: one CTA per (segment, chunk), streaming loads, atomic output ----
__global__ __launch_bounds__(THREADS, 8)
void seg_mean_kernel(const float* __restrict__ x,
                     float* __restrict__ out)
{
    const int b   = blockIdx.x >> 3;          // segment (CHUNKS = 8)
    const int c   = blockIdx.x & (CHUNKS - 1);
    const int tid = threadIdx.x;

    const int start = g_off[b];
    const int len   = g_off[b + 1] - start;
    const int r0    = (int)(((long long)c * len) / CHUNKS);
    const int r1    = (int)(((long long)(c + 1) * len) / CHUNKS);

    const float4* __restrict__ xv =
        reinterpret_cast<const float4*>(x) + (size_t)start * D4;
    const int cg = tid & 31;   // float4 column 0..31
    const int rg = tid >> 5;   // row group 0..3

    float4 a0 = make_float4(0.f, 0.f, 0.f, 0.f);
    float4 a1 = a0, a2 = a0, a3 = a0;

    int r = r0 + rg;
    // 8 independent in-flight streaming LDG.128 per thread, 32 rows/iter
    for (; r + 7 * GROUPS < r1; r += 8 * GROUPS) {
        float4 v0 = __ldcs(&xv[(size_t)(r + 0 * GROUPS) * D4 + cg]);
        float4 v1 = __ldcs(&xv[(size_t)(r + 1 * GROUPS) * D4 + cg]);
        float4 v2 = __ldcs(&xv[(size_t)(r + 2 * GROUPS) * D4 + cg]);
        float4 v3 = __ldcs(&xv[(size_t)(r + 3 * GROUPS) * D4 + cg]);
        float4 v4 = __ldcs(&xv[(size_t)(r + 4 * GROUPS) * D4 + cg]);
        float4 v5 = __ldcs(&xv[(size_t)(r + 5 * GROUPS) * D4 + cg]);
        float4 v6 = __ldcs(&xv[(size_t)(r + 6 * GROUPS) * D4 + cg]);
        float4 v7 = __ldcs(&xv[(size_t)(r + 7 * GROUPS) * D4 + cg]);
        a0.x += v0.x; a0.y += v0.y; a0.z += v0.z; a0.w += v0.w;
        a1.x += v1.x; a1.y += v1.y; a1.z += v1.z; a1.w += v1.w;
        a2.x += v2.x; a2.y += v2.y; a2.z += v2.z; a2.w += v2.w;
        a3.x += v3.x; a3.y += v3.y; a3.z += v3.z; a3.w += v3.w;
        a0.x += v4.x; a0.y += v4.y; a0.z += v4.z; a0.w += v4.w;
        a1.x += v5.x; a1.y += v5.y; a1.z += v5.z; a1.w += v5.w;
        a2.x += v6.x; a2.y += v6.y; a2.z += v6.z; a2.w += v6.w;
        a3.x += v7.x; a3.y += v7.y; a3.z += v7.z; a3.w += v7.w;
    }
    for (; r < r1; r += GROUPS) {
        float4 v = __ldcs(&xv[(size_t)r * D4 + cg]);
        a0.x += v.x; a0.y += v.y; a0.z += v.z; a0.w += v.w;
    }
    a0.x += a1.x + a2.x + a3.x;
    a0.y += a1.y + a2.y + a3.y;
    a0.z += a1.z + a2.z + a3.z;
    a0.w += a1.w + a2.w + a3.w;

    // ---- cross-row-group reduction in smem ----
    __shared__ float4 sred[GROUPS][32];
    sred[rg][cg] = a0;
    __syncthreads();

    if (tid < 32) {
        float4 s = sred[0][tid];
        #pragma unroll
        for (int g = 1; g < GROUPS; g++) {
            float4 v = sred[g][tid];
            s.x += v.x; s.y += v.y; s.z += v.z; s.w += v.w;
        }
        const float inv = 1.0f / (float)len;
        float* o = out + (size_t)b * D + tid * 4;
        atomicAdd(o + 0, s.x * inv);
        atomicAdd(o + 1, s.y * inv);
        atomicAdd(o + 2, s.z * inv);
        atomicAdd(o + 3, s.w * inv);
    }
}

extern "C" void kernel_launch(void* const* d_in, const int* in_sizes, int n_in,
                              void* d_out, int out_size)
{
    const float* x    = (const float*)d_in[0];
    const int*   lens = (const int*)d_in[1];
    float*       out  = (float*)d_out;
    const int B = in_sizes[1];

    prep_kernel<<<32, 1024>>>(lens, B, out, out_size);
    seg_mean_kernel<<<B * CHUNKS, THREADS>>>(x, out);
}